// round 1
// baseline (speedup 1.0000x reference)
#include <cuda_runtime.h>
#include <math_constants.h>

// Shapes (fixed by the problem)
#define VOCAB   100000
#define DIM     300
#define BATCH   4096
#define SEQ     200
#define KDIM    600      // 2*DIM
#define HIDDEN  1000
#define OUTD    3

// Scratch (device globals: no allocations allowed)
__device__ float g_rep[BATCH * KDIM];    // [4096, 600]
__device__ float g_h[BATCH * HIDDEN];    // [4096, 1000]

// ---------------------------------------------------------------------------
// Kernel 1: embedding gather + mean/max pool.
// One block per batch row; 320 threads; thread d (<300) owns dim d.
// Loads of emb[idx*300 + d] are coalesced across the 300 threads per token.
// ---------------------------------------------------------------------------
__global__ __launch_bounds__(320) void pool_kernel(
    const float* __restrict__ emb,
    const int*   __restrict__ x,
    const int*   __restrict__ lengths)
{
    __shared__ int sidx[SEQ];
    __shared__ int slen;

    const int b   = blockIdx.x;
    const int tid = threadIdx.x;

    if (tid < SEQ) sidx[tid] = x[b * SEQ + tid];
    if (tid == 0)  slen = lengths[b];
    __syncthreads();

    const int len = slen;
    const int d = tid;
    if (d < DIM) {
        float sum = 0.0f;
        float mx  = -CUDART_INF_F;
        #pragma unroll 4
        for (int l = 0; l < SEQ; ++l) {
            float v = __ldg(&emb[(size_t)sidx[l] * DIM + d]);
            sum += v;
            mx = (l < len) ? fmaxf(mx, v) : mx;
        }
        g_rep[(size_t)b * KDIM + d]        = sum / (float)len;
        g_rep[(size_t)b * KDIM + DIM + d]  = mx;
    }
}

// ---------------------------------------------------------------------------
// Kernel 2: H = relu(rep @ W1 + b1)     [4096,600] @ [600,1000]
// Register-tiled fp32 GEMM: 64x64 block tile, BK=16, 4x4 per thread.
// ---------------------------------------------------------------------------
#define BM 64
#define BN 64
#define BK 16

__global__ __launch_bounds__(256) void gemm1_kernel(
    const float* __restrict__ W1,
    const float* __restrict__ b1)
{
    __shared__ float As[BK][BM];   // A stored transposed: As[k][m]
    __shared__ float Bs[BK][BN];

    const int block_row = blockIdx.x * BM;   // 64 tiles of M=4096
    const int block_col = blockIdx.y * BN;   // 16 tiles cover N=1000 (last partial)
    const int tid = threadIdx.x;

    const int tr = tid >> 4;        // 0..15 (thread row within 16x16 grid)
    const int tc = tid & 15;        // 0..15 (thread col)

    // A-tile load mapping: 64 rows x 16 k -> one float4 per thread along K
    const int a_row  = tid >> 2;          // 0..63
    const int a_col4 = (tid & 3) * 4;     // 0,4,8,12
    // B-tile load mapping: 16 k x 64 cols -> one float4 per thread along N
    const int b_row = tid >> 4;           // 0..15
    const int b_col = (tid & 15) * 4;     // 0..60

    float acc[4][4];
    #pragma unroll
    for (int i = 0; i < 4; ++i)
        #pragma unroll
        for (int j = 0; j < 4; ++j) acc[i][j] = 0.0f;

    for (int k0 = 0; k0 < KDIM; k0 += BK) {
        // Load A tile (rep). K=600 is a multiple of 4, so a float4 at ak is
        // either fully in-bounds (ak < 600) or fully out.
        float4 av = make_float4(0.f, 0.f, 0.f, 0.f);
        const int ak = k0 + a_col4;
        if (ak < KDIM)
            av = *(const float4*)(&g_rep[(size_t)(block_row + a_row) * KDIM + ak]);
        As[a_col4 + 0][a_row] = av.x;
        As[a_col4 + 1][a_row] = av.y;
        As[a_col4 + 2][a_row] = av.z;
        As[a_col4 + 3][a_row] = av.w;

        // Load B tile (W1). N=1000 multiple of 4 -> no float4 straddle.
        float4 bv = make_float4(0.f, 0.f, 0.f, 0.f);
        const int bk = k0 + b_row;
        const int bc = block_col + b_col;
        if (bk < KDIM && bc < HIDDEN)
            bv = *(const float4*)(&W1[(size_t)bk * HIDDEN + bc]);
        *(float4*)(&Bs[b_row][b_col]) = bv;

        __syncthreads();

        #pragma unroll
        for (int kk = 0; kk < BK; ++kk) {
            float ar[4], br[4];
            *(float4*)ar = *(const float4*)(&As[kk][tr * 4]);
            *(float4*)br = *(const float4*)(&Bs[kk][tc * 4]);
            #pragma unroll
            for (int i = 0; i < 4; ++i)
                #pragma unroll
                for (int j = 0; j < 4; ++j)
                    acc[i][j] = fmaf(ar[i], br[j], acc[i][j]);
        }
        __syncthreads();
    }

    // Epilogue: bias + relu, guarded store (N=1000 not multiple of 64)
    #pragma unroll
    for (int i = 0; i < 4; ++i) {
        const int m = block_row + tr * 4 + i;
        #pragma unroll
        for (int j = 0; j < 4; ++j) {
            const int n = block_col + tc * 4 + j;
            if (n < HIDDEN)
                g_h[(size_t)m * HIDDEN + n] = fmaxf(acc[i][j] + b1[n], 0.0f);
        }
    }
}

// ---------------------------------------------------------------------------
// Kernel 3: out = h @ W2 + b2       [4096,1000] @ [1000,3]
// One warp per batch row; W2 staged in shared; warp-shuffle reduction.
// ---------------------------------------------------------------------------
__global__ __launch_bounds__(256) void gemm2_kernel(
    const float* __restrict__ W2,
    const float* __restrict__ b2,
    float* __restrict__ out)
{
    __shared__ float sW2[HIDDEN * OUTD];   // 12 KB

    const int tid = threadIdx.x;
    for (int i = tid; i < HIDDEN * OUTD; i += 256) sW2[i] = W2[i];
    __syncthreads();

    const int warp = tid >> 5;
    const int lane = tid & 31;
    const int b = blockIdx.x * 8 + warp;

    float a0 = 0.f, a1 = 0.f, a2 = 0.f;
    const float* hrow = &g_h[(size_t)b * HIDDEN];
    #pragma unroll 4
    for (int j = lane; j < HIDDEN; j += 32) {
        float h = hrow[j];
        a0 = fmaf(h, sW2[j * 3 + 0], a0);
        a1 = fmaf(h, sW2[j * 3 + 1], a1);
        a2 = fmaf(h, sW2[j * 3 + 2], a2);
    }
    #pragma unroll
    for (int off = 16; off > 0; off >>= 1) {
        a0 += __shfl_xor_sync(0xFFFFFFFFu, a0, off);
        a1 += __shfl_xor_sync(0xFFFFFFFFu, a1, off);
        a2 += __shfl_xor_sync(0xFFFFFFFFu, a2, off);
    }
    if (lane == 0) {
        out[b * 3 + 0] = a0 + b2[0];
        out[b * 3 + 1] = a1 + b2[1];
        out[b * 3 + 2] = a2 + b2[2];
    }
}

// ---------------------------------------------------------------------------
// Launch. Input order (metadata): emb_table, W1, b1, W2, b2, x, lengths.
// ---------------------------------------------------------------------------
extern "C" void kernel_launch(void* const* d_in, const int* in_sizes, int n_in,
                              void* d_out, int out_size)
{
    const float* emb     = (const float*)d_in[0];
    const float* W1      = (const float*)d_in[1];
    const float* b1      = (const float*)d_in[2];
    const float* W2      = (const float*)d_in[3];
    const float* b2      = (const float*)d_in[4];
    const int*   x       = (const int*)  d_in[5];
    const int*   lengths = (const int*)  d_in[6];
    float*       out     = (float*)d_out;

    pool_kernel<<<BATCH, 320>>>(emb, x, lengths);

    dim3 grid1(BATCH / BM, (HIDDEN + BN - 1) / BN);   // (64, 16)
    gemm1_kernel<<<grid1, 256>>>(W1, b1);

    gemm2_kernel<<<BATCH / 8, 256>>>(W2, b2, out);
}

// round 4
// speedup vs baseline: 1.3103x; 1.3103x over previous
#include <cuda_runtime.h>
#include <math_constants.h>

// Shapes (fixed by the problem)
#define VOCAB   100000
#define DIM     300
#define BATCH   4096
#define SEQ     200
#define KDIM    600      // 2*DIM
#define HIDDEN  1000
#define OUTD    3

// Scratch (device globals: no allocations allowed)
__device__ __align__(16) float g_rep[BATCH * KDIM];    // [4096, 600]
__device__ __align__(16) float g_h[BATCH * HIDDEN];    // [4096, 1000]

typedef unsigned long long ull;

// ---------------------------------------------------------------------------
// L2 evict-last via cache-hint policy (the .v4.f32-compatible form).
// ---------------------------------------------------------------------------
__device__ __forceinline__ ull mk_evict_last_policy() {
    ull pol;
    asm("createpolicy.fractional.L2::evict_last.b64 %0, 1.0;" : "=l"(pol));
    return pol;
}
__device__ __forceinline__ float4 ldg_el(const float4* p, ull pol) {
    float4 v;
    asm("ld.global.nc.L2::cache_hint.v4.f32 {%0,%1,%2,%3}, [%4], %5;"
        : "=f"(v.x), "=f"(v.y), "=f"(v.z), "=f"(v.w) : "l"(p), "l"(pol));
    return v;
}

// ---------------------------------------------------------------------------
// Kernel 1: embedding gather + mean/max pool.
// One block per batch row. 160 threads = 2 groups x 80 (75 active float4 lanes).
// Group g processes tokens [g*100, g*100+100); partials combined in shared.
// Row base = idx*1200 bytes (multiple of 16) -> float4 loads are aligned.
// ---------------------------------------------------------------------------
#define D4 (DIM / 4)            // 75 float4 per row
#define POOL_T 160

__global__ __launch_bounds__(POOL_T) void pool_kernel(
    const float* __restrict__ emb,
    const int*   __restrict__ x,
    const int*   __restrict__ lengths)
{
    __shared__ int    sidx[SEQ];
    __shared__ int    slen;
    __shared__ float4 s_sum[2][D4];
    __shared__ float4 s_max[2][D4];

    const int b   = blockIdx.x;
    const int tid = threadIdx.x;

    for (int i = tid; i < SEQ; i += POOL_T) sidx[i] = x[b * SEQ + i];
    if (tid == 0) slen = lengths[b];
    __syncthreads();

    const int len  = slen;
    const int g    = tid / 80;          // token-group 0/1
    const int lane = tid % 80;          // float4 lane

    const float NEG_INF = __int_as_float(0xff800000);

    if (lane < D4) {
        const ull pol = mk_evict_last_policy();
        const float4* base = (const float4*)emb + lane;
        float4 sum = make_float4(0.f, 0.f, 0.f, 0.f);
        float4 mx  = make_float4(NEG_INF, NEG_INF, NEG_INF, NEG_INF);
        const int l0 = g * 100;
        #pragma unroll 4
        for (int l = 0; l < 100; ++l) {
            const int tok = l0 + l;
            float4 v = ldg_el(base + (size_t)sidx[tok] * D4, pol);
            sum.x += v.x; sum.y += v.y; sum.z += v.z; sum.w += v.w;
            if (tok < len) {
                mx.x = fmaxf(mx.x, v.x); mx.y = fmaxf(mx.y, v.y);
                mx.z = fmaxf(mx.z, v.z); mx.w = fmaxf(mx.w, v.w);
            }
        }
        s_sum[g][lane] = sum;
        s_max[g][lane] = mx;
    }
    __syncthreads();

    if (tid < D4) {
        float4 s0 = s_sum[0][tid], s1 = s_sum[1][tid];
        float4 m0 = s_max[0][tid], m1 = s_max[1][tid];
        const float inv = 1.0f / (float)len;
        float4 mean = make_float4((s0.x + s1.x) * inv, (s0.y + s1.y) * inv,
                                  (s0.z + s1.z) * inv, (s0.w + s1.w) * inv);
        float4 mx   = make_float4(fmaxf(m0.x, m1.x), fmaxf(m0.y, m1.y),
                                  fmaxf(m0.z, m1.z), fmaxf(m0.w, m1.w));
        float4* rep = (float4*)&g_rep[(size_t)b * KDIM];
        rep[tid]      = mean;   // dims [0,300)
        rep[D4 + tid] = mx;     // dims [300,600)
    }
}

// ---------------------------------------------------------------------------
// Kernel 2: H = relu(rep @ W1 + b1)   [4096,600] @ [600,1000]
// 128x64 block tile, BK=16, 8(M)x4(N) per thread, packed fma.rn.f32x2
// (accumulator pairs along M; A pairs load free from shared, B is dup-packed).
// ---------------------------------------------------------------------------
#define BM 128
#define BN 64
#define BK 16

__device__ __forceinline__ ull dup_f32x2(float v) {
    ull r;
    asm("mov.b64 %0, {%1, %1};" : "=l"(r) : "f"(v));
    return r;
}
__device__ __forceinline__ void fma_f32x2(ull& d, ull a, ull b) {
    asm("fma.rn.f32x2 %0, %1, %2, %0;" : "+l"(d) : "l"(a), "l"(b));
}

__global__ __launch_bounds__(256) void gemm1_kernel(
    const float* __restrict__ W1,
    const float* __restrict__ b1)
{
    __shared__ float As[BK][BM];   // A transposed: As[k][m]  (8 KB)
    __shared__ float Bs[BK][BN];   // (4 KB)

    const int block_row = blockIdx.x * BM;
    const int block_col = blockIdx.y * BN;
    const int tid = threadIdx.x;

    const int tr = tid >> 4;        // 0..15 -> rows tr*8..tr*8+7
    const int tc = tid & 15;        // 0..15 -> cols tc*4..tc*4+3

    // B-tile load map: 16 k x 64 n, one float4 per thread
    const int b_row = tid >> 4;
    const int b_col = (tid & 15) * 4;

    ull acc[4][4];                  // [M-pair][N], each holds 2 M-rows
    #pragma unroll
    for (int i = 0; i < 4; ++i)
        #pragma unroll
        for (int j = 0; j < 4; ++j) acc[i][j] = 0ULL;

    for (int k0 = 0; k0 < KDIM; k0 += BK) {
        // A tile: 128 rows x 16 k = 512 float4; 2 per thread
        #pragma unroll
        for (int u = 0; u < 2; ++u) {
            const int idx    = tid * 2 + u;
            const int a_row  = idx >> 2;
            const int a_col4 = (idx & 3) * 4;
            const int ak     = k0 + a_col4;
            float4 av = make_float4(0.f, 0.f, 0.f, 0.f);
            if (ak < KDIM)
                av = *(const float4*)(&g_rep[(size_t)(block_row + a_row) * KDIM + ak]);
            As[a_col4 + 0][a_row] = av.x;
            As[a_col4 + 1][a_row] = av.y;
            As[a_col4 + 2][a_row] = av.z;
            As[a_col4 + 3][a_row] = av.w;
        }
        // B tile
        {
            const int bk = k0 + b_row;
            const int bc = block_col + b_col;
            float4 bv = make_float4(0.f, 0.f, 0.f, 0.f);
            if (bk < KDIM && bc < HIDDEN)
                bv = *(const float4*)(&W1[(size_t)bk * HIDDEN + bc]);
            *(float4*)(&Bs[b_row][b_col]) = bv;
        }
        __syncthreads();

        #pragma unroll
        for (int kk = 0; kk < BK; ++kk) {
            // 8 A floats = 4 packed f32x2 (aligned shared load, no packing)
            const ull* ap = (const ull*)(&As[kk][tr * 8]);
            ull a01 = ap[0], a23 = ap[1], a45 = ap[2], a67 = ap[3];
            float4 bv = *(const float4*)(&Bs[kk][tc * 4]);
            ull bd0 = dup_f32x2(bv.x), bd1 = dup_f32x2(bv.y);
            ull bd2 = dup_f32x2(bv.z), bd3 = dup_f32x2(bv.w);
            fma_f32x2(acc[0][0], a01, bd0); fma_f32x2(acc[0][1], a01, bd1);
            fma_f32x2(acc[0][2], a01, bd2); fma_f32x2(acc[0][3], a01, bd3);
            fma_f32x2(acc[1][0], a23, bd0); fma_f32x2(acc[1][1], a23, bd1);
            fma_f32x2(acc[1][2], a23, bd2); fma_f32x2(acc[1][3], a23, bd3);
            fma_f32x2(acc[2][0], a45, bd0); fma_f32x2(acc[2][1], a45, bd1);
            fma_f32x2(acc[2][2], a45, bd2); fma_f32x2(acc[2][3], a45, bd3);
            fma_f32x2(acc[3][0], a67, bd0); fma_f32x2(acc[3][1], a67, bd1);
            fma_f32x2(acc[3][2], a67, bd2); fma_f32x2(acc[3][3], a67, bd3);
        }
        __syncthreads();
    }

    // Epilogue: bias + relu, guarded store (N tail)
    #pragma unroll
    for (int i = 0; i < 4; ++i) {
        const int m0 = block_row + tr * 8 + 2 * i;
        #pragma unroll
        for (int j = 0; j < 4; ++j) {
            const int n = block_col + tc * 4 + j;
            if (n < HIDDEN) {
                float2 p = *(float2*)&acc[i][j];
                const float bias = b1[n];
                g_h[(size_t)(m0 + 0) * HIDDEN + n] = fmaxf(p.x + bias, 0.0f);
                g_h[(size_t)(m0 + 1) * HIDDEN + n] = fmaxf(p.y + bias, 0.0f);
            }
        }
    }
}

// ---------------------------------------------------------------------------
// Kernel 3: out = h @ W2 + b2       [4096,1000] @ [1000,3]
// One warp per batch row; W2 staged in shared; warp-shuffle reduction.
// ---------------------------------------------------------------------------
__global__ __launch_bounds__(256) void gemm2_kernel(
    const float* __restrict__ W2,
    const float* __restrict__ b2,
    float* __restrict__ out)
{
    __shared__ float sW2[HIDDEN * OUTD];   // 12 KB

    const int tid = threadIdx.x;
    for (int i = tid; i < HIDDEN * OUTD; i += 256) sW2[i] = W2[i];
    __syncthreads();

    const int warp = tid >> 5;
    const int lane = tid & 31;
    const int b = blockIdx.x * 8 + warp;

    float a0 = 0.f, a1 = 0.f, a2 = 0.f;
    const float* hrow = &g_h[(size_t)b * HIDDEN];
    #pragma unroll 4
    for (int j = lane; j < HIDDEN; j += 32) {
        float h = hrow[j];
        a0 = fmaf(h, sW2[j * 3 + 0], a0);
        a1 = fmaf(h, sW2[j * 3 + 1], a1);
        a2 = fmaf(h, sW2[j * 3 + 2], a2);
    }
    #pragma unroll
    for (int off = 16; off > 0; off >>= 1) {
        a0 += __shfl_xor_sync(0xFFFFFFFFu, a0, off);
        a1 += __shfl_xor_sync(0xFFFFFFFFu, a1, off);
        a2 += __shfl_xor_sync(0xFFFFFFFFu, a2, off);
    }
    if (lane == 0) {
        out[b * 3 + 0] = a0 + b2[0];
        out[b * 3 + 1] = a1 + b2[1];
        out[b * 3 + 2] = a2 + b2[2];
    }
}

// ---------------------------------------------------------------------------
// Launch. Input order (metadata): emb_table, W1, b1, W2, b2, x, lengths.
// ---------------------------------------------------------------------------
extern "C" void kernel_launch(void* const* d_in, const int* in_sizes, int n_in,
                              void* d_out, int out_size)
{
    const float* emb     = (const float*)d_in[0];
    const float* W1      = (const float*)d_in[1];
    const float* b1      = (const float*)d_in[2];
    const float* W2      = (const float*)d_in[3];
    const float* b2      = (const float*)d_in[4];
    const int*   x       = (const int*)  d_in[5];
    const int*   lengths = (const int*)  d_in[6];
    float*       out     = (float*)d_out;

    pool_kernel<<<BATCH, POOL_T>>>(emb, x, lengths);

    dim3 grid1(BATCH / BM, (HIDDEN + BN - 1) / BN);   // (32, 16)
    gemm1_kernel<<<grid1, 256>>>(W1, b1);

    gemm2_kernel<<<BATCH / 8, 256>>>(W2, b2, out);
}

// round 8
// speedup vs baseline: 1.9229x; 1.4675x over previous
#include <cuda_runtime.h>
#include <cuda_bf16.h>
#include <math_constants.h>
#include <cstdint>

// Shapes (fixed by the problem)
#define VOCAB   100000
#define DIM     300
#define BATCH   4096
#define SEQ     200
#define KDIM    600      // 2*DIM
#define HIDDEN  1000
#define OUTD    3

// Split-bf16 GEMM1 geometry
#define KP      1824     // padded K' = 3*600 -> 1824 (57 x 32)
#define KC      32       // K elems per SMEM stage
#define NSTAGES (KP / KC)   // 57
#define BM      128
#define BN      128
#define NPAD    1024     // padded N (8 x 128)
#define SKP     40       // smem row stride in bf16 (32 + 8 pad) -> conflict-free ldmatrix

// Scratch (device globals: no allocations allowed)
__device__ __align__(16) __nv_bfloat16 g_A [BATCH * KP];   // [4096,1824] A' = [Ahi|Ahi|Alo]
__device__ __align__(16) __nv_bfloat16 g_Wt[NPAD * KP];    // [1024,1824] W' = [Whi|Wlo|Whi] (K-major)
__device__ __align__(16) float g_h[(size_t)BATCH * HIDDEN];

typedef unsigned long long ull;

// ===========================================================================
// Small PTX helpers
// ===========================================================================
__device__ __forceinline__ uint32_t smem_u32(const void* p) {
    uint32_t a;
    asm("{ .reg .u64 t; cvta.to.shared.u64 t, %1; cvt.u32.u64 %0, t; }" : "=r"(a) : "l"(p));
    return a;
}
__device__ __forceinline__ void ldsm_x4(uint32_t& r0, uint32_t& r1, uint32_t& r2,
                                        uint32_t& r3, uint32_t addr) {
    asm volatile("ldmatrix.sync.aligned.m8n8.x4.shared.b16 {%0,%1,%2,%3}, [%4];"
                 : "=r"(r0), "=r"(r1), "=r"(r2), "=r"(r3) : "r"(addr));
}
__device__ __forceinline__ void mma_bf16(float& c0, float& c1, float& c2, float& c3,
                                         uint32_t a0, uint32_t a1, uint32_t a2, uint32_t a3,
                                         uint32_t b0, uint32_t b1) {
    asm volatile("mma.sync.aligned.m16n8k16.row.col.f32.bf16.bf16.f32 "
                 "{%0,%1,%2,%3}, {%4,%5,%6,%7}, {%8,%9}, {%0,%1,%2,%3};"
                 : "+f"(c0), "+f"(c1), "+f"(c2), "+f"(c3)
                 : "r"(a0), "r"(a1), "r"(a2), "r"(a3), "r"(b0), "r"(b1));
}

// ===========================================================================
// Pool (gather + mean/max) fused with A' bf16 hi/lo emission
// ===========================================================================
__device__ __forceinline__ ull mk_evict_last_policy() {
    ull pol;
    asm("createpolicy.fractional.L2::evict_last.b64 %0, 1.0;" : "=l"(pol));
    return pol;
}
__device__ __forceinline__ float4 ldg_el(const float4* p, ull pol) {
    float4 v;
    asm("ld.global.nc.L2::cache_hint.v4.f32 {%0,%1,%2,%3}, [%4], %5;"
        : "=f"(v.x), "=f"(v.y), "=f"(v.z), "=f"(v.w) : "l"(p), "l"(pol));
    return v;
}

// write 4 floats at A'[row][k..k+3] in hi/hi/lo form
__device__ __forceinline__ void store_hilo4(size_t rowb, int k, float4 v) {
    __nv_bfloat16 h0 = __float2bfloat16(v.x), h1 = __float2bfloat16(v.y);
    __nv_bfloat16 h2 = __float2bfloat16(v.z), h3 = __float2bfloat16(v.w);
    __nv_bfloat16 l0 = __float2bfloat16(v.x - __bfloat162float(h0));
    __nv_bfloat16 l1 = __float2bfloat16(v.y - __bfloat162float(h1));
    __nv_bfloat16 l2 = __float2bfloat16(v.z - __bfloat162float(h2));
    __nv_bfloat16 l3 = __float2bfloat16(v.w - __bfloat162float(h3));
    __nv_bfloat162 hA = __halves2bfloat162(h0, h1), hB = __halves2bfloat162(h2, h3);
    __nv_bfloat162 lA = __halves2bfloat162(l0, l1), lB = __halves2bfloat162(l2, l3);
    *(__nv_bfloat162*)&g_A[rowb + k]             = hA;
    *(__nv_bfloat162*)&g_A[rowb + k + 2]         = hB;
    *(__nv_bfloat162*)&g_A[rowb + 600 + k]       = hA;
    *(__nv_bfloat162*)&g_A[rowb + 600 + k + 2]   = hB;
    *(__nv_bfloat162*)&g_A[rowb + 1200 + k]      = lA;
    *(__nv_bfloat162*)&g_A[rowb + 1200 + k + 2]  = lB;
}

#define D4 (DIM / 4)            // 75 float4 per row
#define POOL_T 160

__global__ __launch_bounds__(POOL_T) void pool_kernel(
    const float* __restrict__ emb,
    const int*   __restrict__ x,
    const int*   __restrict__ lengths)
{
    __shared__ int    sidx[SEQ];
    __shared__ int    slen;
    __shared__ float4 s_sum[2][D4];
    __shared__ float4 s_max[2][D4];

    const int b   = blockIdx.x;
    const int tid = threadIdx.x;

    for (int i = tid; i < SEQ; i += POOL_T) sidx[i] = x[b * SEQ + i];
    if (tid == 0) slen = lengths[b];
    __syncthreads();

    const int len  = slen;
    const int g    = tid / 80;
    const int lane = tid % 80;
    const float NEG_INF = __int_as_float(0xff800000);

    if (lane < D4) {
        const ull pol = mk_evict_last_policy();
        const float4* base = (const float4*)emb + lane;
        float4 sum = make_float4(0.f, 0.f, 0.f, 0.f);
        float4 mx  = make_float4(NEG_INF, NEG_INF, NEG_INF, NEG_INF);
        const int l0 = g * 100;
        #pragma unroll 4
        for (int l = 0; l < 100; ++l) {
            const int tok = l0 + l;
            float4 v = ldg_el(base + (size_t)sidx[tok] * D4, pol);
            sum.x += v.x; sum.y += v.y; sum.z += v.z; sum.w += v.w;
            if (tok < len) {
                mx.x = fmaxf(mx.x, v.x); mx.y = fmaxf(mx.y, v.y);
                mx.z = fmaxf(mx.z, v.z); mx.w = fmaxf(mx.w, v.w);
            }
        }
        s_sum[g][lane] = sum;
        s_max[g][lane] = mx;
    }
    __syncthreads();

    const size_t rowb = (size_t)b * KP;
    if (tid < D4) {
        float4 s0 = s_sum[0][tid], s1 = s_sum[1][tid];
        float4 m0 = s_max[0][tid], m1 = s_max[1][tid];
        const float inv = 1.0f / (float)len;
        float4 mean = make_float4((s0.x + s1.x) * inv, (s0.y + s1.y) * inv,
                                  (s0.z + s1.z) * inv, (s0.w + s1.w) * inv);
        float4 mx   = make_float4(fmaxf(m0.x, m1.x), fmaxf(m0.y, m1.y),
                                  fmaxf(m0.z, m1.z), fmaxf(m0.w, m1.w));
        store_hilo4(rowb, 4 * tid, mean);            // k' = d
        store_hilo4(rowb, DIM + 4 * tid, mx);        // k' = 300 + d
    }
    // zero-pad K' [1800,1824)
    if (tid >= 80 && tid < 92) {
        const int k = 1800 + (tid - 80) * 2;
        *(__nv_bfloat162*)&g_A[rowb + k] =
            __halves2bfloat162(__float2bfloat16(0.f), __float2bfloat16(0.f));
    }
}

// ===========================================================================
// W' prep: g_Wt[n][k'] K-major, [Whi | Wlo | Whi], rows n>=1000 zero
// ===========================================================================
__global__ __launch_bounds__(256) void wprep_kernel(const float* __restrict__ W1)
{
    const int n = blockIdx.x;                 // 0..1023
    __nv_bfloat16* dst = &g_Wt[(size_t)n * KP];
    for (int k = threadIdx.x; k < KP; k += 256) {
        __nv_bfloat16 o = __float2bfloat16(0.f);
        if (n < HIDDEN) {
            if (k < 600) {
                o = __float2bfloat16(W1[(size_t)k * HIDDEN + n]);
            } else if (k < 1200) {
                float v = W1[(size_t)(k - 600) * HIDDEN + n];
                __nv_bfloat16 h = __float2bfloat16(v);
                o = __float2bfloat16(v - __bfloat162float(h));
            } else if (k < 1800) {
                o = __float2bfloat16(W1[(size_t)(k - 1200) * HIDDEN + n]);
            }
        }
        dst[k] = o;
    }
}

// ===========================================================================
// GEMM1: h = relu(A' @ W'^T + b1) via mma.sync bf16 (m16n8k16).
// 128x128 block, 8 warps (2M x 4N), 64x32 warp tile, KC=32 double-buffered.
// ===========================================================================
__global__ __launch_bounds__(256) void gemm1_kernel(const float* __restrict__ b1)
{
    __shared__ __nv_bfloat16 As[2][BM][SKP];   // 2 x 10240 B
    __shared__ __nv_bfloat16 Bs[2][BN][SKP];   // 2 x 10240 B

    const int tid  = threadIdx.x;
    const int warp = tid >> 5;
    const int lane = tid & 31;
    const int wm   = warp >> 2;       // 0..1
    const int wn   = warp & 3;        // 0..3
    const int block_row = blockIdx.x * BM;
    const int block_col = blockIdx.y * BN;

    // Global-load mapping: per tile 128 rows x 32 k = 512 uint4; 2 per thread.
    const int r0 = (tid >> 2);            // u=0 row
    const int c0 = (tid & 3) * 8;         // bf16 col
    // u=1: row r0+64, same col.

    const __nv_bfloat16* gA0 = &g_A [(size_t)(block_row + r0)      * KP + c0];
    const __nv_bfloat16* gA1 = &g_A [(size_t)(block_row + r0 + 64) * KP + c0];
    const __nv_bfloat16* gB0 = &g_Wt[(size_t)(block_col + r0)      * KP + c0];
    const __nv_bfloat16* gB1 = &g_Wt[(size_t)(block_col + r0 + 64) * KP + c0];

    // ldmatrix per-lane coordinates
    const int a_m = lane & 15;                          // row within 16
    const int a_k = (lane >> 4) << 3;                   // 0 or 8
    const int b_n = ((lane >> 4) << 3) + (lane & 7);    // row within 16 (n)
    const int b_k = lane & 8;                           // 0 or 8

    float acc[4][4][4];
    #pragma unroll
    for (int i = 0; i < 4; ++i)
        #pragma unroll
        for (int j = 0; j < 4; ++j)
            #pragma unroll
            for (int e = 0; e < 4; ++e) acc[i][j][e] = 0.0f;

    // Preload stage 0
    {
        *(uint4*)&As[0][r0     ][c0] = *(const uint4*)gA0;
        *(uint4*)&As[0][r0 + 64][c0] = *(const uint4*)gA1;
        *(uint4*)&Bs[0][r0     ][c0] = *(const uint4*)gB0;
        *(uint4*)&Bs[0][r0 + 64][c0] = *(const uint4*)gB1;
    }
    __syncthreads();

    for (int s = 0; s < NSTAGES; ++s) {
        const int buf = s & 1;
        uint4 pa0, pa1, pb0, pb1;
        const bool more = (s + 1 < NSTAGES);
        if (more) {
            const size_t koff = (size_t)(s + 1) * KC;
            pa0 = *(const uint4*)(gA0 + koff);
            pa1 = *(const uint4*)(gA1 + koff);
            pb0 = *(const uint4*)(gB0 + koff);
            pb1 = *(const uint4*)(gB1 + koff);
        }

        #pragma unroll
        for (int q = 0; q < 2; ++q) {                 // two k16 steps
            const int kq = q * 16;
            uint32_t a[4][4];
            #pragma unroll
            for (int i = 0; i < 4; ++i) {
                const uint32_t addr = smem_u32(
                    &As[buf][wm * 64 + i * 16 + a_m][kq + a_k]);
                ldsm_x4(a[i][0], a[i][1], a[i][2], a[i][3], addr);
            }
            uint32_t bfr[4][2];
            #pragma unroll
            for (int p = 0; p < 2; ++p) {             // pairs of n8 tiles
                const uint32_t addr = smem_u32(
                    &Bs[buf][wn * 32 + p * 16 + b_n][kq + b_k]);
                uint32_t t0, t1, t2, t3;
                ldsm_x4(t0, t1, t2, t3, addr);
                bfr[p * 2 + 0][0] = t0; bfr[p * 2 + 0][1] = t1;
                bfr[p * 2 + 1][0] = t2; bfr[p * 2 + 1][1] = t3;
            }
            #pragma unroll
            for (int i = 0; i < 4; ++i)
                #pragma unroll
                for (int j = 0; j < 4; ++j)
                    mma_bf16(acc[i][j][0], acc[i][j][1], acc[i][j][2], acc[i][j][3],
                             a[i][0], a[i][1], a[i][2], a[i][3],
                             bfr[j][0], bfr[j][1]);
        }

        if (more) {
            const int nb = buf ^ 1;
            *(uint4*)&As[nb][r0     ][c0] = pa0;
            *(uint4*)&As[nb][r0 + 64][c0] = pa1;
            *(uint4*)&Bs[nb][r0     ][c0] = pb0;
            *(uint4*)&Bs[nb][r0 + 64][c0] = pb1;
        }
        __syncthreads();
    }

    // Epilogue: bias + relu -> g_h[m][n] (row-major), float2 stores
    const int mq = lane >> 2;            // 0..7
    const int nq = (lane & 3) * 2;       // 0,2,4,6
    #pragma unroll
    for (int j = 0; j < 4; ++j) {
        const int n = block_col + wn * 32 + j * 8 + nq;
        if (n >= HIDDEN) continue;
        const float bn0 = b1[n], bn1 = b1[n + 1];
        #pragma unroll
        for (int i = 0; i < 4; ++i) {
            const int m = block_row + wm * 64 + i * 16 + mq;
            float2 v0, v1;
            v0.x = fmaxf(acc[i][j][0] + bn0, 0.0f);
            v0.y = fmaxf(acc[i][j][1] + bn1, 0.0f);
            v1.x = fmaxf(acc[i][j][2] + bn0, 0.0f);
            v1.y = fmaxf(acc[i][j][3] + bn1, 0.0f);
            *(float2*)&g_h[(size_t)m * HIDDEN + n]       = v0;
            *(float2*)&g_h[(size_t)(m + 8) * HIDDEN + n] = v1;
        }
    }
}

// ===========================================================================
// GEMM2: out = h @ W2 + b2       [4096,1000] @ [1000,3]
// One warp per batch row; W2 staged in shared; warp-shuffle reduction.
// ===========================================================================
__global__ __launch_bounds__(256) void gemm2_kernel(
    const float* __restrict__ W2,
    const float* __restrict__ b2,
    float* __restrict__ out)
{
    __shared__ float sW2[HIDDEN * OUTD];   // 12 KB

    const int tid = threadIdx.x;
    for (int i = tid; i < HIDDEN * OUTD; i += 256) sW2[i] = W2[i];
    __syncthreads();

    const int warp = tid >> 5;
    const int lane = tid & 31;
    const int b = blockIdx.x * 8 + warp;

    float a0 = 0.f, a1 = 0.f, a2 = 0.f;
    const float* hrow = &g_h[(size_t)b * HIDDEN];
    #pragma unroll 4
    for (int j = lane; j < HIDDEN; j += 32) {
        float h = hrow[j];
        a0 = fmaf(h, sW2[j * 3 + 0], a0);
        a1 = fmaf(h, sW2[j * 3 + 1], a1);
        a2 = fmaf(h, sW2[j * 3 + 2], a2);
    }
    #pragma unroll
    for (int off = 16; off > 0; off >>= 1) {
        a0 += __shfl_xor_sync(0xFFFFFFFFu, a0, off);
        a1 += __shfl_xor_sync(0xFFFFFFFFu, a1, off);
        a2 += __shfl_xor_sync(0xFFFFFFFFu, a2, off);
    }
    if (lane == 0) {
        out[b * 3 + 0] = a0 + b2[0];
        out[b * 3 + 1] = a1 + b2[1];
        out[b * 3 + 2] = a2 + b2[2];
    }
}

// ===========================================================================
// Launch. Input order (metadata): emb_table, W1, b1, W2, b2, x, lengths.
// ===========================================================================
extern "C" void kernel_launch(void* const* d_in, const int* in_sizes, int n_in,
                              void* d_out, int out_size)
{
    const float* emb     = (const float*)d_in[0];
    const float* W1      = (const float*)d_in[1];
    const float* b1      = (const float*)d_in[2];
    const float* W2      = (const float*)d_in[3];
    const float* b2      = (const float*)d_in[4];
    const int*   x       = (const int*)  d_in[5];
    const int*   lengths = (const int*)  d_in[6];
    float*       out     = (float*)d_out;

    wprep_kernel<<<NPAD, 256>>>(W1);                 // independent of pool
    pool_kernel<<<BATCH, POOL_T>>>(emb, x, lengths);
    gemm1_kernel<<<dim3(BATCH / BM, NPAD / BN), 256>>>(b1);   // (32, 8)
    gemm2_kernel<<<BATCH / 8, 256>>>(W2, b2, out);
}

// round 10
// speedup vs baseline: 2.0766x; 1.0800x over previous
#include <cuda_runtime.h>
#include <cuda_bf16.h>
#include <math_constants.h>
#include <cstdint>

// Shapes (fixed by the problem)
#define VOCAB   100000
#define DIM     300
#define BATCH   4096
#define SEQ     200
#define KDIM    600      // 2*DIM
#define HIDDEN  1000
#define OUTD    3

// Split-bf16 GEMM1 geometry
#define KP      1824     // padded K' = 3*600 -> 1824 (57 x 32)
#define KC      32       // K elems per SMEM stage
#define NSTAGES (KP / KC)   // 57
#define BM      128
#define BN      128
#define NPAD    1024     // padded N (8 x 128)
#define NTILES  (NPAD / BN)  // 8
#define SKP     40       // smem row stride in bf16 (32 + 8 pad) -> conflict-free ldmatrix

// Scratch (device globals: no allocations allowed)
__device__ __align__(16) __nv_bfloat16 g_A [BATCH * KP];   // [4096,1824] A' = [Ahi|Ahi|Alo]
__device__ __align__(16) __nv_bfloat16 g_Wt[NPAD * KP];    // [1024,1824] W' = [Whi|Wlo|Whi] (K-major)
__device__ __align__(16) float g_part[NTILES * BATCH * OUTD];  // fused-gemm2 partials

typedef unsigned long long ull;

// ===========================================================================
// Small PTX helpers
// ===========================================================================
__device__ __forceinline__ uint32_t smem_u32(const void* p) {
    uint32_t a;
    asm("{ .reg .u64 t; cvta.to.shared.u64 t, %1; cvt.u32.u64 %0, t; }" : "=r"(a) : "l"(p));
    return a;
}
__device__ __forceinline__ void ldsm_x4(uint32_t& r0, uint32_t& r1, uint32_t& r2,
                                        uint32_t& r3, uint32_t addr) {
    asm volatile("ldmatrix.sync.aligned.m8n8.x4.shared.b16 {%0,%1,%2,%3}, [%4];"
                 : "=r"(r0), "=r"(r1), "=r"(r2), "=r"(r3) : "r"(addr));
}
__device__ __forceinline__ void mma_bf16(float& c0, float& c1, float& c2, float& c3,
                                         uint32_t a0, uint32_t a1, uint32_t a2, uint32_t a3,
                                         uint32_t b0, uint32_t b1) {
    asm volatile("mma.sync.aligned.m16n8k16.row.col.f32.bf16.bf16.f32 "
                 "{%0,%1,%2,%3}, {%4,%5,%6,%7}, {%8,%9}, {%0,%1,%2,%3};"
                 : "+f"(c0), "+f"(c1), "+f"(c2), "+f"(c3)
                 : "r"(a0), "r"(a1), "r"(a2), "r"(a3), "r"(b0), "r"(b1));
}

// ===========================================================================
// Pool (gather + mean/max) fused with A' bf16 hi/lo emission
// ===========================================================================
__device__ __forceinline__ ull mk_evict_last_policy() {
    ull pol;
    asm("createpolicy.fractional.L2::evict_last.b64 %0, 1.0;" : "=l"(pol));
    return pol;
}
__device__ __forceinline__ float4 ldg_el(const float4* p, ull pol) {
    float4 v;
    asm("ld.global.nc.L2::cache_hint.v4.f32 {%0,%1,%2,%3}, [%4], %5;"
        : "=f"(v.x), "=f"(v.y), "=f"(v.z), "=f"(v.w) : "l"(p), "l"(pol));
    return v;
}

// write 4 floats at A'[row][k..k+3] in hi/hi/lo form
__device__ __forceinline__ void store_hilo4(size_t rowb, int k, float4 v) {
    __nv_bfloat16 h0 = __float2bfloat16(v.x), h1 = __float2bfloat16(v.y);
    __nv_bfloat16 h2 = __float2bfloat16(v.z), h3 = __float2bfloat16(v.w);
    __nv_bfloat16 l0 = __float2bfloat16(v.x - __bfloat162float(h0));
    __nv_bfloat16 l1 = __float2bfloat16(v.y - __bfloat162float(h1));
    __nv_bfloat16 l2 = __float2bfloat16(v.z - __bfloat162float(h2));
    __nv_bfloat16 l3 = __float2bfloat16(v.w - __bfloat162float(h3));
    __nv_bfloat162 hA = __halves2bfloat162(h0, h1), hB = __halves2bfloat162(h2, h3);
    __nv_bfloat162 lA = __halves2bfloat162(l0, l1), lB = __halves2bfloat162(l2, l3);
    *(__nv_bfloat162*)&g_A[rowb + k]             = hA;
    *(__nv_bfloat162*)&g_A[rowb + k + 2]         = hB;
    *(__nv_bfloat162*)&g_A[rowb + 600 + k]       = hA;
    *(__nv_bfloat162*)&g_A[rowb + 600 + k + 2]   = hB;
    *(__nv_bfloat162*)&g_A[rowb + 1200 + k]      = lA;
    *(__nv_bfloat162*)&g_A[rowb + 1200 + k + 2]  = lB;
}

#define D4 (DIM / 4)            // 75 float4 per row
#define POOL_T 160

__global__ __launch_bounds__(POOL_T) void pool_kernel(
    const float* __restrict__ emb,
    const int*   __restrict__ x,
    const int*   __restrict__ lengths)
{
    __shared__ int    sidx[SEQ];
    __shared__ int    slen;
    __shared__ float4 s_sum[2][D4];
    __shared__ float4 s_max[2][D4];

    const int b   = blockIdx.x;
    const int tid = threadIdx.x;

    for (int i = tid; i < SEQ; i += POOL_T) sidx[i] = x[b * SEQ + i];
    if (tid == 0) slen = lengths[b];
    __syncthreads();

    const int len  = slen;
    const int g    = tid / 80;
    const int lane = tid % 80;
    const float NEG_INF = __int_as_float(0xff800000);

    if (lane < D4) {
        const ull pol = mk_evict_last_policy();
        const float4* base = (const float4*)emb + lane;
        float4 sum = make_float4(0.f, 0.f, 0.f, 0.f);
        float4 mx  = make_float4(NEG_INF, NEG_INF, NEG_INF, NEG_INF);
        const int l0 = g * 100;
        #pragma unroll 4
        for (int l = 0; l < 100; ++l) {
            const int tok = l0 + l;
            float4 v = ldg_el(base + (size_t)sidx[tok] * D4, pol);
            sum.x += v.x; sum.y += v.y; sum.z += v.z; sum.w += v.w;
            if (tok < len) {
                mx.x = fmaxf(mx.x, v.x); mx.y = fmaxf(mx.y, v.y);
                mx.z = fmaxf(mx.z, v.z); mx.w = fmaxf(mx.w, v.w);
            }
        }
        s_sum[g][lane] = sum;
        s_max[g][lane] = mx;
    }
    __syncthreads();

    const size_t rowb = (size_t)b * KP;
    if (tid < D4) {
        float4 s0 = s_sum[0][tid], s1 = s_sum[1][tid];
        float4 m0 = s_max[0][tid], m1 = s_max[1][tid];
        const float inv = 1.0f / (float)len;
        float4 mean = make_float4((s0.x + s1.x) * inv, (s0.y + s1.y) * inv,
                                  (s0.z + s1.z) * inv, (s0.w + s1.w) * inv);
        float4 mx   = make_float4(fmaxf(m0.x, m1.x), fmaxf(m0.y, m1.y),
                                  fmaxf(m0.z, m1.z), fmaxf(m0.w, m1.w));
        store_hilo4(rowb, 4 * tid, mean);            // k' = d
        store_hilo4(rowb, DIM + 4 * tid, mx);        // k' = 300 + d
    }
    // zero-pad K' [1800,1824)
    if (tid >= 80 && tid < 92) {
        const int k = 1800 + (tid - 80) * 2;
        *(__nv_bfloat162*)&g_A[rowb + k] =
            __halves2bfloat162(__float2bfloat16(0.f), __float2bfloat16(0.f));
    }
}

// ===========================================================================
// W' prep: g_Wt[n][k'] K-major, [Whi | Wlo | Whi], rows n>=1000 zero
// ===========================================================================
__global__ __launch_bounds__(256) void wprep_kernel(const float* __restrict__ W1)
{
    const int n = blockIdx.x;                 // 0..1023
    __nv_bfloat16* dst = &g_Wt[(size_t)n * KP];
    for (int k = threadIdx.x; k < KP; k += 256) {
        __nv_bfloat16 o = __float2bfloat16(0.f);
        if (n < HIDDEN) {
            if (k < 600) {
                o = __float2bfloat16(W1[(size_t)k * HIDDEN + n]);
            } else if (k < 1200) {
                float v = W1[(size_t)(k - 600) * HIDDEN + n];
                __nv_bfloat16 h = __float2bfloat16(v);
                o = __float2bfloat16(v - __bfloat162float(h));
            } else if (k < 1800) {
                o = __float2bfloat16(W1[(size_t)(k - 1200) * HIDDEN + n]);
            }
        }
        dst[k] = o;
    }
}

// ===========================================================================
// GEMM1 (fused): partial_out = relu(A' @ W'^T + b1) @ W2, per N-tile.
// 128x128 block, 8 warps (2M x 4N), 64x32 warp tile, KC=32 double-buffered.
// h never hits global memory.
// ===========================================================================
__global__ __launch_bounds__(256) void gemm1_fused_kernel(
    const float* __restrict__ b1,
    const float* __restrict__ W2)
{
    __shared__ __nv_bfloat16 As[2][BM][SKP];   // 2 x 10240 B
    __shared__ __nv_bfloat16 Bs[2][BN][SKP];   // 2 x 10240 B
    __shared__ float s_red[4][BM][OUTD];       // 6 KB (per-wn partials)

    const int tid  = threadIdx.x;
    const int warp = tid >> 5;
    const int lane = tid & 31;
    const int wm   = warp >> 2;       // 0..1
    const int wn   = warp & 3;        // 0..3
    const int block_row = blockIdx.x * BM;
    const int block_col = blockIdx.y * BN;

    // Global-load mapping: per tile 128 rows x 32 k = 512 uint4; 2 per thread.
    const int r0 = (tid >> 2);            // u=0 row
    const int c0 = (tid & 3) * 8;         // bf16 col

    const __nv_bfloat16* gA0 = &g_A [(size_t)(block_row + r0)      * KP + c0];
    const __nv_bfloat16* gA1 = &g_A [(size_t)(block_row + r0 + 64) * KP + c0];
    const __nv_bfloat16* gB0 = &g_Wt[(size_t)(block_col + r0)      * KP + c0];
    const __nv_bfloat16* gB1 = &g_Wt[(size_t)(block_col + r0 + 64) * KP + c0];

    // ldmatrix per-lane coordinates
    const int a_m = lane & 15;                          // row within 16
    const int a_k = (lane >> 4) << 3;                   // 0 or 8
    const int b_n = ((lane >> 4) << 3) + (lane & 7);    // row within 16 (n)
    const int b_k = lane & 8;                           // 0 or 8

    float acc[4][4][4];
    #pragma unroll
    for (int i = 0; i < 4; ++i)
        #pragma unroll
        for (int j = 0; j < 4; ++j)
            #pragma unroll
            for (int e = 0; e < 4; ++e) acc[i][j][e] = 0.0f;

    // Preload stage 0
    {
        *(uint4*)&As[0][r0     ][c0] = *(const uint4*)gA0;
        *(uint4*)&As[0][r0 + 64][c0] = *(const uint4*)gA1;
        *(uint4*)&Bs[0][r0     ][c0] = *(const uint4*)gB0;
        *(uint4*)&Bs[0][r0 + 64][c0] = *(const uint4*)gB1;
    }
    __syncthreads();

    for (int s = 0; s < NSTAGES; ++s) {
        const int buf = s & 1;
        uint4 pa0, pa1, pb0, pb1;
        const bool more = (s + 1 < NSTAGES);
        if (more) {
            const size_t koff = (size_t)(s + 1) * KC;
            pa0 = *(const uint4*)(gA0 + koff);
            pa1 = *(const uint4*)(gA1 + koff);
            pb0 = *(const uint4*)(gB0 + koff);
            pb1 = *(const uint4*)(gB1 + koff);
        }

        #pragma unroll
        for (int q = 0; q < 2; ++q) {                 // two k16 steps
            const int kq = q * 16;
            uint32_t a[4][4];
            #pragma unroll
            for (int i = 0; i < 4; ++i) {
                const uint32_t addr = smem_u32(
                    &As[buf][wm * 64 + i * 16 + a_m][kq + a_k]);
                ldsm_x4(a[i][0], a[i][1], a[i][2], a[i][3], addr);
            }
            uint32_t bfr[4][2];
            #pragma unroll
            for (int p = 0; p < 2; ++p) {             // pairs of n8 tiles
                const uint32_t addr = smem_u32(
                    &Bs[buf][wn * 32 + p * 16 + b_n][kq + b_k]);
                uint32_t t0, t1, t2, t3;
                ldsm_x4(t0, t1, t2, t3, addr);
                bfr[p * 2 + 0][0] = t0; bfr[p * 2 + 0][1] = t1;
                bfr[p * 2 + 1][0] = t2; bfr[p * 2 + 1][1] = t3;
            }
            #pragma unroll
            for (int i = 0; i < 4; ++i)
                #pragma unroll
                for (int j = 0; j < 4; ++j)
                    mma_bf16(acc[i][j][0], acc[i][j][1], acc[i][j][2], acc[i][j][3],
                             a[i][0], a[i][1], a[i][2], a[i][3],
                             bfr[j][0], bfr[j][1]);
        }

        if (more) {
            const int nb = buf ^ 1;
            *(uint4*)&As[nb][r0     ][c0] = pa0;
            *(uint4*)&As[nb][r0 + 64][c0] = pa1;
            *(uint4*)&Bs[nb][r0     ][c0] = pb0;
            *(uint4*)&Bs[nb][r0 + 64][c0] = pb1;
        }
        __syncthreads();
    }

    // ---- Fused epilogue: p[m][c] = sum_n relu(acc + b1[n]) * W2[n][c] ----
    const int mq = lane >> 2;            // 0..7
    const int nq = (lane & 3) * 2;       // 0,2,4,6

    float part[8][OUTD];                 // r = i*2 + e_hi -> m rows
    #pragma unroll
    for (int r = 0; r < 8; ++r)
        #pragma unroll
        for (int c = 0; c < OUTD; ++c) part[r][c] = 0.0f;

    #pragma unroll
    for (int j = 0; j < 4; ++j) {
        const int n0 = block_col + wn * 32 + j * 8 + nq;   // even; n1 = n0+1
        float bn0 = 0.f, bn1 = 0.f;
        float w0[OUTD] = {0.f, 0.f, 0.f}, w1[OUTD] = {0.f, 0.f, 0.f};
        if (n0 < HIDDEN) {
            bn0 = b1[n0]; bn1 = b1[n0 + 1];
            #pragma unroll
            for (int c = 0; c < OUTD; ++c) {
                w0[c] = W2[n0 * OUTD + c];
                w1[c] = W2[(n0 + 1) * OUTD + c];
            }
        }
        #pragma unroll
        for (int i = 0; i < 4; ++i) {
            const float h00 = fmaxf(acc[i][j][0] + bn0, 0.0f);
            const float h01 = fmaxf(acc[i][j][1] + bn1, 0.0f);
            const float h10 = fmaxf(acc[i][j][2] + bn0, 0.0f);
            const float h11 = fmaxf(acc[i][j][3] + bn1, 0.0f);
            #pragma unroll
            for (int c = 0; c < OUTD; ++c) {
                part[i * 2 + 0][c] = fmaf(h00, w0[c], fmaf(h01, w1[c], part[i * 2 + 0][c]));
                part[i * 2 + 1][c] = fmaf(h10, w0[c], fmaf(h11, w1[c], part[i * 2 + 1][c]));
            }
        }
    }

    // reduce across the 4 lanes (nq groups) sharing each m-row (deterministic)
    #pragma unroll
    for (int r = 0; r < 8; ++r)
        #pragma unroll
        for (int c = 0; c < OUTD; ++c) {
            float v = part[r][c];
            v += __shfl_xor_sync(0xFFFFFFFFu, v, 1);
            v += __shfl_xor_sync(0xFFFFFFFFu, v, 2);
            part[r][c] = v;
        }

    if ((lane & 3) == 0) {
        #pragma unroll
        for (int r = 0; r < 8; ++r) {
            const int row = wm * 64 + (r >> 1) * 16 + mq + (r & 1) * 8;
            #pragma unroll
            for (int c = 0; c < OUTD; ++c) s_red[wn][row][c] = part[r][c];
        }
    }
    __syncthreads();

    // sum the 4 wn slices; one (row, c) per thread (384 needed, have 256: loop)
    for (int idx = tid; idx < BM * OUTD; idx += 256) {
        const int row = idx / OUTD, c = idx % OUTD;
        const float v = s_red[0][row][c] + s_red[1][row][c]
                      + s_red[2][row][c] + s_red[3][row][c];
        g_part[((size_t)blockIdx.y * BATCH + (block_row + row)) * OUTD + c] = v;
    }
}

// ===========================================================================
// Final reduce: out[m][c] = b2[c] + sum_z g_part[z][m][c]   (fixed order)
// ===========================================================================
__global__ __launch_bounds__(256) void out_reduce_kernel(
    const float* __restrict__ b2,
    float* __restrict__ out)
{
    const int m = blockIdx.x * 256 + threadIdx.x;
    float a0 = b2[0], a1 = b2[1], a2 = b2[2];
    #pragma unroll
    for (int z = 0; z < NTILES; ++z) {
        const size_t o = ((size_t)z * BATCH + m) * OUTD;
        a0 += g_part[o + 0]; a1 += g_part[o + 1]; a2 += g_part[o + 2];
    }
    out[m * 3 + 0] = a0; out[m * 3 + 1] = a1; out[m * 3 + 2] = a2;
}

// ===========================================================================
// Launch. Input order (metadata): emb_table, W1, b1, W2, b2, x, lengths.
// ===========================================================================
extern "C" void kernel_launch(void* const* d_in, const int* in_sizes, int n_in,
                              void* d_out, int out_size)
{
    const float* emb     = (const float*)d_in[0];
    const float* W1      = (const float*)d_in[1];
    const float* b1      = (const float*)d_in[2];
    const float* W2      = (const float*)d_in[3];
    const float* b2      = (const float*)d_in[4];
    const int*   x       = (const int*)  d_in[5];
    const int*   lengths = (const int*)  d_in[6];
    float*       out     = (float*)d_out;

    wprep_kernel<<<NPAD, 256>>>(W1);                 // independent of pool
    pool_kernel<<<BATCH, POOL_T>>>(emb, x, lengths);
    gemm1_fused_kernel<<<dim3(BATCH / BM, NTILES), 256>>>(b1, W2);  // (32, 8)
    out_reduce_kernel<<<BATCH / 256, 256>>>(b2, out);
}